// round 14
// baseline (speedup 1.0000x reference)
#include <cuda_runtime.h>
#include <cuda_fp16.h>
#include <math.h>
#include <stdint.h>

#define NT 8192
#define DD 1024
#define CSPLIT 128        // iter-1 column-partial chunks
#define CH 512            // fast-iter row chunks
#define RPC (NT / CH)     // 16 rows per chunk

typedef __half fp16;

// ---------------- scratch (device globals; blocked operand layouts) --------
// A-type: [mblk=M/128][ch=32][128 rows x 32 fp16 (64B rows), swizzled] 8192 B
// B-type: [nblk=N/256][ch=32][256 rows x 32 fp16 (64B rows), swizzled] 16384 B
__device__ __align__(256) fp16 g_e1[(size_t)NT * DD], g_e2[(size_t)NT * DD];
__device__ __align__(256) fp16 g_t1[(size_t)NT * DD], g_t2[(size_t)NT * DD];
__device__ __align__(256) fp16 g_a1[(size_t)NT * DD], g_a2[(size_t)NT * DD];
__device__ __align__(256) fp16 g_b1[(size_t)NT * DD], g_b2[(size_t)NT * DD];
__device__ __align__(256) fp16 g_w1a[(size_t)DD * DD], g_w1b[(size_t)DD * DD];
__device__ __align__(256) fp16 g_w2a[(size_t)DD * DD], g_w2b[(size_t)DD * DD];
__device__ float  g_r[NT];
__device__ float  g_c[NT];
__device__ float  g_cz[NT];
__device__ float  g_p[(size_t)CH * NT];
__device__ float2 g_p2[(size_t)CSPLIT * NT];

// ---------------- helpers ----------------
__device__ __forceinline__ uint32_t smem_u32(const void* p) {
    uint32_t a;
    asm("{ .reg .u64 t; cvta.to.shared.u64 t, %1; cvt.u32.u64 %0, t; }"
        : "=r"(a) : "l"(p));
    return a;
}
__device__ __forceinline__ void ldsm4(uint32_t& r0, uint32_t& r1,
                                      uint32_t& r2, uint32_t& r3, uint32_t a) {
    asm volatile("ldmatrix.sync.aligned.m8n8.x4.shared.b16 {%0,%1,%2,%3}, [%4];"
                 : "=r"(r0), "=r"(r1), "=r"(r2), "=r"(r3) : "r"(a));
}
__device__ __forceinline__ void mma16816(float* d, const uint32_t* a,
                                         const uint32_t* b) {
    asm volatile(
        "mma.sync.aligned.m16n8k16.row.col.f32.f16.f16.f32 "
        "{%0,%1,%2,%3}, {%4,%5,%6,%7}, {%8,%9}, {%0,%1,%2,%3};"
        : "+f"(d[0]), "+f"(d[1]), "+f"(d[2]), "+f"(d[3])
        : "r"(a[0]), "r"(a[1]), "r"(a[2]), "r"(a[3]), "r"(b[0]), "r"(b[1]));
}
__device__ __forceinline__ void mbar_init(uint32_t mb) {
    asm volatile("mbarrier.init.shared.b64 [%0], %1;"
                 :: "r"(mb), "r"(1u) : "memory");
}
__device__ __forceinline__ void mbar_inval(uint32_t mb) {
    asm volatile("mbarrier.inval.shared.b64 [%0];" :: "r"(mb) : "memory");
}
__device__ __forceinline__ void mbar_expect(uint32_t mb, uint32_t tx) {
    asm volatile("mbarrier.arrive.expect_tx.shared.b64 _, [%0], %1;"
                 :: "r"(mb), "r"(tx) : "memory");
}
__device__ __forceinline__ void mbar_wait(uint32_t mb, uint32_t phase) {
    asm volatile(
        "{\n\t.reg .pred P;\n\t"
        "WL_%=:\n\t"
        "mbarrier.try_wait.parity.acquire.cta.shared::cta.b64 P, [%0], %1, 0x989680;\n\t"
        "@P bra.uni WD_%=;\n\t"
        "bra.uni WL_%=;\n\t"
        "WD_%=:\n\t}"
        :: "r"(mb), "r"(phase) : "memory");
}
__device__ __forceinline__ void bulk_cp(uint32_t dst, const void* src,
                                        uint32_t bytes, uint32_t mb) {
    asm volatile(
        "cp.async.bulk.shared::cluster.global.mbarrier::complete_tx::bytes "
        "[%0], [%1], %2, [%3];"
        :: "r"(dst), "l"(src), "r"(bytes), "r"(mb) : "memory");
}

__device__ __forceinline__ void split1(float v, fp16& h1, fp16& h2)
{
    h1 = __float2half_rn(v);
    h2 = __float2half_rn(v - __half2float(h1));
}
// swizzled byte offset within a 64B-row tile block:
// 16B granule index = (4*(r&1) + (cg ^ ((r>>1)&3))) mod 8 -> 8 distinct rows
__device__ __forceinline__ uint32_t swz32(uint32_t row, uint32_t colbyte)
{
    return row * 64 + (colbyte ^ (((row >> 1) & 3) << 4));
}

// ================= GEMM geometry =================
#define BKC 32
#define NCHK (DD / BKC)          // 32
#define ABLK 8192                // bytes per A block (128x32 fp16)
#define BBLK 16384               // bytes per B block (256x32 fp16)
#define STG (2 * ABLK + 2 * BBLK)    // 49152 bytes
#define NSTG 4
#define MM_SMEM (NSTG * STG + 64)    // 196672

// ================= split emb -> A-type blocked fp16x2 =================
__global__ void __launch_bounds__(256)
split2(const float* __restrict__ x, fp16* __restrict__ o1,
       fp16* __restrict__ o2)
{
    size_t uid = (size_t)blockIdx.x * 256 + threadIdx.x;  // 16B-granule id
    int row = (int)(uid >> 7);          // 128 granules per row (1024/8)
    int k0 = (int)(uid & 127) * 8;
    const float4* xs = (const float4*)(x + (size_t)row * DD + k0);
    float4 v0 = xs[0], v1 = xs[1];
    float vv[8] = {v0.x, v0.y, v0.z, v0.w, v1.x, v1.y, v1.z, v1.w};
    fp16 h1[8], h2[8];
#pragma unroll
    for (int k = 0; k < 8; k++) split1(vv[k], h1[k], h2[k]);
    size_t blk = ((size_t)(row >> 7) * NCHK + (k0 >> 5)) * ABLK;
    uint32_t ph = swz32(row & 127, (k0 & 31) * 2);
    *(uint4*)((char*)o1 + blk + ph) = *(uint4*)h1;
    *(uint4*)((char*)o2 + blk + ph) = *(uint4*)h2;
}

// ========== transpose + split W [K,N] -> B-type blocked Wt[N,K] ============
__global__ void __launch_bounds__(256)
tsplit(const float* __restrict__ W, fp16* __restrict__ o1,
       fp16* __restrict__ o2)
{
    __shared__ float tile[32][33];
    const int bn = blockIdx.x * 32;
    const int bk = blockIdx.y * 32;
    const int tx = threadIdx.x, ty = threadIdx.y;   // 32 x 8
#pragma unroll
    for (int i = 0; i < 32; i += 8)
        tile[ty + i][tx] = W[(size_t)(bk + ty + i) * DD + bn + tx];
    __syncthreads();
#pragma unroll
    for (int i = 0; i < 32; i += 8) {
        float v = tile[tx][ty + i];
        fp16 h1, h2;
        split1(v, h1, h2);
        int n = bn + ty + i, k = bk + tx;
        size_t blk = ((size_t)(n >> 8) * NCHK + (k >> 5)) * BBLK;
        uint32_t ph = swz32(n & 255, (k & 31) * 2);
        *(fp16*)((char*)o1 + blk + ph) = h1;
        *(fp16*)((char*)o2 + blk + ph) = h2;
    }
}

// ================= mma.sync fp16x3-pair GEMM: acc = A · B^T ================
// CTA tile 128x256, 256 thr, warp tile 64x64, BK=32, 4-stage bulk-copy pipe.
enum { EPI_SCORE = 0, EPI_GELU = 1, EPI_BIAS = 2 };

template <int EPI, int OBLK>
__global__ void __launch_bounds__(256, 1)
mma_gemm(const fp16* __restrict__ A1, const fp16* __restrict__ A2,
         const fp16* __restrict__ B1, const fp16* __restrict__ B2,
         const float* __restrict__ bias, float* __restrict__ Cf,
         fp16* __restrict__ O1, fp16* __restrict__ O2, int ldc)
{
    extern __shared__ __align__(128) char sm[];
    const uint32_t sS = smem_u32(sm);
    const uint32_t sMB = sS + NSTG * STG;
    const int tid = threadIdx.x;
    const int wid = tid >> 5, lane = tid & 31;
    const int bm = blockIdx.y * 128, bn = blockIdx.x * 256;
    const int wm = (wid & 1) * 64, wn = (wid >> 1) * 64;

    const char* srcA1 = (const char*)A1 + (size_t)blockIdx.y * NCHK * ABLK;
    const char* srcA2 = (const char*)A2 + (size_t)blockIdx.y * NCHK * ABLK;
    const char* srcB1 = (const char*)B1 + (size_t)blockIdx.x * NCHK * BBLK;
    const char* srcB2 = (const char*)B2 + (size_t)blockIdx.x * NCHK * BBLK;

    float acc[4][8][4];
#pragma unroll
    for (int i = 0; i < 4; i++)
#pragma unroll
        for (int j = 0; j < 8; j++)
#pragma unroll
            for (int k = 0; k < 4; k++) acc[i][j][k] = 0.0f;

    if (tid == 0) {
#pragma unroll
        for (int s = 0; s < NSTG; s++) mbar_init(sMB + s * 8);
    }
    __syncthreads();

    auto arm_load = [&](int ch) {
        int stage = ch & (NSTG - 1);
        uint32_t mb = sMB + stage * 8;
        mbar_expect(mb, STG);
        uint32_t so = sS + stage * STG;
        bulk_cp(so + 0 * ABLK,        srcA1 + (size_t)ch * ABLK, ABLK, mb);
        bulk_cp(so + 1 * ABLK,        srcA2 + (size_t)ch * ABLK, ABLK, mb);
        bulk_cp(so + 2 * ABLK,        srcB1 + (size_t)ch * BBLK, BBLK, mb);
        bulk_cp(so + 2 * ABLK + BBLK, srcB2 + (size_t)ch * BBLK, BBLK, mb);
    };

    if (tid == 0) {
        arm_load(0);
        arm_load(1);
        arm_load(2);
    }

    for (int ch = 0; ch < NCHK; ch++) {
        const int stage = ch & (NSTG - 1);
        mbar_wait(sMB + stage * 8, (ch >> 2) & 1);

        const uint32_t so = sS + stage * STG;
        const uint32_t sA1 = so, sA2 = so + ABLK;
        const uint32_t sB1 = so + 2 * ABLK, sB2 = sB1 + BBLK;

#pragma unroll
        for (int kt = 0; kt < 2; kt++) {
            uint32_t afA[2][4][4];
#pragma unroll
            for (int mt = 0; mt < 4; mt++) {
                uint32_t row = (uint32_t)(wm + mt * 16 + (lane & 15));
                uint32_t ph = swz32(row, kt * 32 + (lane >> 4) * 16);
                ldsm4(afA[0][mt][0], afA[0][mt][1], afA[0][mt][2],
                      afA[0][mt][3], sA1 + ph);
                ldsm4(afA[1][mt][0], afA[1][mt][1], afA[1][mt][2],
                      afA[1][mt][3], sA2 + ph);
            }
#pragma unroll
            for (int np = 0; np < 4; np++) {
                uint32_t rowb = (uint32_t)(wn + np * 16 + (lane & 7) +
                                           ((lane >> 4) << 3));
                uint32_t ph = swz32(rowb, kt * 32 + ((lane >> 3) & 1) * 16);
                uint32_t b1f[4], b2f[4];
                ldsm4(b1f[0], b1f[1], b1f[2], b1f[3], sB1 + ph);
                ldsm4(b2f[0], b2f[1], b2f[2], b2f[3], sB2 + ph);
#pragma unroll
                for (int half = 0; half < 2; half++) {
                    uint32_t bv[2] = {b1f[half * 2], b1f[half * 2 + 1]};
#pragma unroll
                    for (int mt = 0; mt < 4; mt++)
                        mma16816(acc[mt][np * 2 + half], afA[0][mt], bv);
                }
#pragma unroll
                for (int half = 0; half < 2; half++) {
                    uint32_t bv[2] = {b2f[half * 2], b2f[half * 2 + 1]};
#pragma unroll
                    for (int mt = 0; mt < 4; mt++)
                        mma16816(acc[mt][np * 2 + half], afA[0][mt], bv);
                }
#pragma unroll
                for (int half = 0; half < 2; half++) {
                    uint32_t bv[2] = {b1f[half * 2], b1f[half * 2 + 1]};
#pragma unroll
                    for (int mt = 0; mt < 4; mt++)
                        mma16816(acc[mt][np * 2 + half], afA[1][mt], bv);
                }
            }
        }
        __syncthreads();
        // arm ch+3 into the stage freed by ch-1 (all warps just synced past ch)
        if (ch + 3 < NCHK && tid == 0) arm_load(ch + 3);
    }

    // epilogue
#pragma unroll
    for (int mt = 0; mt < 4; mt++) {
#pragma unroll
        for (int nt = 0; nt < 8; nt++) {
            int row = bm + wm + mt * 16 + (lane >> 2);
            int col = bn + wn + nt * 8 + (lane & 3) * 2;
            float* d = acc[mt][nt];
            if (EPI == EPI_SCORE) {
                *(float2*)&Cf[(size_t)row * ldc + col] =
                    make_float2(d[0] * 20.0f, d[1] * 20.0f);
                *(float2*)&Cf[(size_t)(row + 8) * ldc + col] =
                    make_float2(d[2] * 20.0f, d[3] * 20.0f);
            } else {
                float bx = bias[col], by = bias[col + 1];
                float v[4] = {d[0] + bx, d[1] + by, d[2] + bx, d[3] + by};
                if (EPI == EPI_GELU) {
#pragma unroll
                    for (int k = 0; k < 4; k++)
                        v[k] = 0.5f * v[k] *
                               (1.0f + erff(v[k] * 0.70710678118654752f));
                }
#pragma unroll
                for (int h = 0; h < 2; h++) {
                    int rr = row + 8 * h;
                    fp16 s1[2], s2[2];
                    split1(v[2 * h + 0], s1[0], s2[0]);
                    split1(v[2 * h + 1], s1[1], s2[1]);
                    size_t blk;
                    uint32_t ph;
                    if (OBLK == 128) {
                        blk = ((size_t)(rr >> 7) * NCHK + (col >> 5)) * ABLK;
                        ph = swz32(rr & 127, (col & 31) * 2);
                    } else {
                        blk = ((size_t)(rr >> 8) * NCHK + (col >> 5)) * BBLK;
                        ph = swz32(rr & 255, (col & 31) * 2);
                    }
                    *(uint32_t*)((char*)O1 + blk + ph) = *(uint32_t*)s1;
                    *(uint32_t*)((char*)O2 + blk + ph) = *(uint32_t*)s2;
                }
            }
        }
    }
    __syncthreads();
    if (tid == 0) {
#pragma unroll
        for (int s = 0; s < NSTG; s++) mbar_inval(sMB + s * 8);
    }
}

// ================= Sinkhorn (R5-R13 proven) =================
__device__ __forceinline__ void lse_upd(float& m, float& l, float v)
{
    if (v <= m) {
        l += __expf(v - m);
    } else {
        l = fmaf(l, __expf(m - v), 1.0f);
        m = v;
    }
}

__global__ void zero_vec(float* __restrict__ c)
{
    c[blockIdx.x * 256 + threadIdx.x] = 0.0f;
}

__global__ void __launch_bounds__(256)
row_lse_kernel(const float* __restrict__ S, const float* __restrict__ c,
               float* __restrict__ r)
{
    const int row = blockIdx.x;
    const int tid = threadIdx.x;
    const float4* s4 = (const float4*)(S + (size_t)row * NT);
    const float4* c4 = (const float4*)c;

    float m = -INFINITY, l = 0.0f;
    for (int j = tid; j < NT / 4; j += 256) {
        float4 s = s4[j];
        float4 cc = c4[j];
        lse_upd(m, l, s.x - cc.x);
        lse_upd(m, l, s.y - cc.y);
        lse_upd(m, l, s.z - cc.z);
        lse_upd(m, l, s.w - cc.w);
    }

    __shared__ float sm[256], sl[256];
    sm[tid] = m; sl[tid] = l;
    __syncthreads();
    for (int s = 128; s > 0; s >>= 1) {
        if (tid < s) {
            float m2 = sm[tid + s], l2 = sl[tid + s];
            float nm = fmaxf(sm[tid], m2);
            sl[tid] = sl[tid] * __expf(sm[tid] - nm) + l2 * __expf(m2 - nm);
            sm[tid] = nm;
        }
        __syncthreads();
    }
    if (tid == 0) r[row] = sm[0] + __logf(sl[0]);
}

__global__ void __launch_bounds__(256)
col_lse_partial_kernel(const float* __restrict__ S, const float* __restrict__ r,
                       float2* __restrict__ part)
{
    const int j4 = blockIdx.x * blockDim.x + threadIdx.x;
    const int chunk = blockIdx.y;
    const int rowsPer = NT / CSPLIT;
    const int i0 = chunk * rowsPer;

    float m0 = -INFINITY, m1 = -INFINITY, m2 = -INFINITY, m3 = -INFINITY;
    float l0 = 0.f, l1 = 0.f, l2 = 0.f, l3 = 0.f;

    const float4* S4 = (const float4*)S;
    for (int i = i0; i < i0 + rowsPer; i++) {
        float4 s = S4[(size_t)i * (NT / 4) + j4];
        float rv = __ldg(&r[i]);
        lse_upd(m0, l0, s.x - rv);
        lse_upd(m1, l1, s.y - rv);
        lse_upd(m2, l2, s.z - rv);
        lse_upd(m3, l3, s.w - rv);
    }
    int j = j4 * 4;
    float2* p = part + (size_t)chunk * NT + j;
    p[0] = make_float2(m0, l0);
    p[1] = make_float2(m1, l1);
    p[2] = make_float2(m2, l2);
    p[3] = make_float2(m3, l3);
}

__global__ void __launch_bounds__(256)
col_lse_combine_kernel(const float2* __restrict__ part, float* __restrict__ c)
{
    const int j = blockIdx.x * blockDim.x + threadIdx.x;
    float m = -INFINITY, l = 0.0f;
    for (int k = 0; k < CSPLIT; k++) {
        float2 p = part[(size_t)k * NT + j];
        float nm = fmaxf(m, p.x);
        l = l * __expf(m - nm) + p.y * __expf(p.x - nm);
        m = nm;
    }
    c[j] = m + __logf(l);
}

__device__ __forceinline__ float blk_sum(float x, float* sb, int tid)
{
#pragma unroll
    for (int o = 16; o; o >>= 1) x += __shfl_down_sync(0xffffffffu, x, o);
    if ((tid & 31) == 0) sb[tid >> 5] = x;
    __syncthreads();
    if (tid < 32) {
        float y = (tid < 8) ? sb[tid] : 0.0f;
#pragma unroll
        for (int o = 4; o; o >>= 1) y += __shfl_down_sync(0xffffffffu, y, o);
        if (tid == 0) sb[32] = y;
    }
    __syncthreads();
    float r = sb[32];
    __syncthreads();
    return r;
}

__global__ void __launch_bounds__(256)
sink_fast(const float* __restrict__ S, float* __restrict__ r,
          const float* __restrict__ c, float* __restrict__ part)
{
    __shared__ float cc[NT];
    __shared__ float sb[40];
    const int tid = threadIdx.x, chunk = blockIdx.x;

    for (int k = tid; k < NT / 4; k += 256)
        ((float4*)cc)[k] = ((const float4*)c)[k];
    __syncthreads();

    float acc[32];
#pragma unroll
    for (int k = 0; k < 32; k++) acc[k] = 0.0f;

    for (int i = chunk * RPC; i < chunk * RPC + RPC; i++) {
        const float4* S4 = (const float4*)(S + (size_t)i * NT);
        const float rr = r[i];
        float4 e[8];
        float dot = 0.0f;
#pragma unroll
        for (int q = 0; q < 8; q++) {
            float4 s = S4[tid + 256 * q];
            float4 cv = *(const float4*)&cc[4 * (tid + 256 * q)];
            e[q].x = __expf(s.x - cv.x - rr);
            e[q].y = __expf(s.y - cv.y - rr);
            e[q].z = __expf(s.z - cv.z - rr);
            e[q].w = __expf(s.w - cv.w - rr);
            dot += (e[q].x + e[q].y) + (e[q].z + e[q].w);
        }
        dot = blk_sum(dot, sb, tid);
        float w = __fdividef(1.0f, dot);
        if (tid == 0) r[i] = rr + __logf(dot);
#pragma unroll
        for (int q = 0; q < 8; q++) {
            acc[4 * q + 0] = fmaf(e[q].x, w, acc[4 * q + 0]);
            acc[4 * q + 1] = fmaf(e[q].y, w, acc[4 * q + 1]);
            acc[4 * q + 2] = fmaf(e[q].z, w, acc[4 * q + 2]);
            acc[4 * q + 3] = fmaf(e[q].w, w, acc[4 * q + 3]);
        }
    }
    float* pp = part + (size_t)chunk * NT;
#pragma unroll
    for (int q = 0; q < 8; q++) {
        int j = 4 * (tid + 256 * q);
        *(float4*)&pp[j] = make_float4(acc[4 * q + 0], acc[4 * q + 1],
                                       acc[4 * q + 2], acc[4 * q + 3]);
    }
}

__global__ void __launch_bounds__(256)
comb_add(const float* __restrict__ part, float* __restrict__ c)
{
    const int j = blockIdx.x * 256 + threadIdx.x;
    float s = 0.0f;
    for (int k = 0; k < CH; k++) s += part[(size_t)k * NT + j];
    c[j] += __logf(s);
}

__global__ void __launch_bounds__(256)
final_exp_kernel(float* __restrict__ S, const float* __restrict__ r,
                 const float* __restrict__ c)
{
    size_t idx = (size_t)blockIdx.x * blockDim.x + threadIdx.x;
    int row = (int)(idx >> 11);
    int j4 = (int)(idx & 2047);
    float4 s = ((const float4*)S)[idx];
    float rv = r[row];
    float4 cc = ((const float4*)c)[j4];
    s.x = __expf(s.x - rv - cc.x);
    s.y = __expf(s.y - rv - cc.y);
    s.z = __expf(s.z - rv - cc.z);
    s.w = __expf(s.w - rv - cc.w);
    ((float4*)S)[idx] = s;
}

// ---------------- launch ----------------
extern "C" void kernel_launch(void* const* d_in, const int* in_sizes, int n_in,
                              void* d_out, int out_size)
{
    const float* emb_a = (const float*)d_in[0];
    const float* emb_b = (const float*)d_in[1];
    const float* W1    = (const float*)d_in[2];
    const float* b1    = (const float*)d_in[3];
    const float* W2    = (const float*)d_in[4];
    const float* b2    = (const float*)d_in[5];
    float* out = (float*)d_out;

    float *r, *c, *cz, *p;
    float2* p2;
    fp16 *e1, *e2, *t1, *t2, *a1, *a2, *bb1, *bb2;
    fp16 *w1a, *w1b, *w2a, *w2b;
    cudaGetSymbolAddress((void**)&r, g_r);
    cudaGetSymbolAddress((void**)&c, g_c);
    cudaGetSymbolAddress((void**)&cz, g_cz);
    cudaGetSymbolAddress((void**)&p, g_p);
    cudaGetSymbolAddress((void**)&p2, g_p2);
    cudaGetSymbolAddress((void**)&e1, g_e1);
    cudaGetSymbolAddress((void**)&e2, g_e2);
    cudaGetSymbolAddress((void**)&t1, g_t1);
    cudaGetSymbolAddress((void**)&t2, g_t2);
    cudaGetSymbolAddress((void**)&a1, g_a1);
    cudaGetSymbolAddress((void**)&a2, g_a2);
    cudaGetSymbolAddress((void**)&bb1, g_b1);
    cudaGetSymbolAddress((void**)&bb2, g_b2);
    cudaGetSymbolAddress((void**)&w1a, g_w1a);
    cudaGetSymbolAddress((void**)&w1b, g_w1b);
    cudaGetSymbolAddress((void**)&w2a, g_w2a);
    cudaGetSymbolAddress((void**)&w2b, g_w2b);

    cudaFuncSetAttribute(mma_gemm<EPI_SCORE, 128>,
                         cudaFuncAttributeMaxDynamicSharedMemorySize, MM_SMEM);
    cudaFuncSetAttribute(mma_gemm<EPI_GELU, 128>,
                         cudaFuncAttributeMaxDynamicSharedMemorySize, MM_SMEM);
    cudaFuncSetAttribute(mma_gemm<EPI_BIAS, 128>,
                         cudaFuncAttributeMaxDynamicSharedMemorySize, MM_SMEM);
    cudaFuncSetAttribute(mma_gemm<EPI_BIAS, 256>,
                         cudaFuncAttributeMaxDynamicSharedMemorySize, MM_SMEM);

    dim3 blk(256);
    dim3 tblk(32, 8);
    dim3 tgrid(DD / 32, DD / 32);
    dim3 grid_mlp(DD / 256, NT / 128);   // (4, 64)
    dim3 grid_big(NT / 256, NT / 128);   // (32, 64)
    unsigned nsplit = (unsigned)((size_t)NT * DD / 8 / 256);   // 4096

    // weight transpose + split (once)
    tsplit<<<tgrid, tblk>>>(W1, w1a, w1b);
    tsplit<<<tgrid, tblk>>>(W2, w2a, w2b);

    // ---- projection of emb_a ----
    split2<<<nsplit, blk>>>(emb_a, e1, e2);
    mma_gemm<EPI_GELU, 128><<<grid_mlp, blk, MM_SMEM>>>(
        e1, e2, w1a, w1b, b1, nullptr, t1, t2, DD);
    mma_gemm<EPI_BIAS, 128><<<grid_mlp, blk, MM_SMEM>>>(
        t1, t2, w2a, w2b, b2, nullptr, a1, a2, DD);

    // ---- projection of emb_b ----
    split2<<<nsplit, blk>>>(emb_b, e1, e2);
    mma_gemm<EPI_GELU, 128><<<grid_mlp, blk, MM_SMEM>>>(
        e1, e2, w1a, w1b, b1, nullptr, t1, t2, DD);
    mma_gemm<EPI_BIAS, 256><<<grid_mlp, blk, MM_SMEM>>>(
        t1, t2, w2a, w2b, b2, nullptr, bb1, bb2, DD);

    // ---- scores = (a @ b^T) * 20 ----
    mma_gemm<EPI_SCORE, 128><<<grid_big, blk, MM_SMEM>>>(
        a1, a2, bb1, bb2, nullptr, out, nullptr, nullptr, NT);

    // ---- Sinkhorn iteration 1 (exact, overflow-safe) ----
    zero_vec<<<NT / 256, blk>>>(cz);
    row_lse_kernel<<<NT, blk>>>(out, cz, r);
    col_lse_partial_kernel<<<dim3((NT / 4) / 256, CSPLIT), blk>>>(out, r, p2);
    col_lse_combine_kernel<<<NT / 256, blk>>>(p2, c);

    // ---- iterations 2..20: fused fast path ----
    for (int it = 0; it < 19; it++) {
        sink_fast<<<CH, blk>>>(out, r, c, p);
        comb_add<<<NT / 256, blk>>>(p, c);
    }

    final_exp_kernel<<<(unsigned)((size_t)NT * NT / 4 / 256), blk>>>(out, r, c);
}

// round 15
// speedup vs baseline: 1.0311x; 1.0311x over previous
#include <cuda_runtime.h>
#include <cuda_fp16.h>
#include <math.h>
#include <stdint.h>

#define NT 8192
#define DD 1024
#define CSPLIT 128        // iter-1 column-partial chunks
#define CH 512            // fast-iter row chunks
#define RPC (NT / CH)     // 16 rows per chunk

typedef __half fp16;

// ---------------- scratch (device globals; blocked operand layout) ---------
// All operands: [blk=dim/128][ch=32][128 rows x 32 fp16 (64B rows), swizzled]
__device__ __align__(256) fp16 g_e1[(size_t)NT * DD], g_e2[(size_t)NT * DD];
__device__ __align__(256) fp16 g_t1[(size_t)NT * DD], g_t2[(size_t)NT * DD];
__device__ __align__(256) fp16 g_a1[(size_t)NT * DD], g_a2[(size_t)NT * DD];
__device__ __align__(256) fp16 g_b1[(size_t)NT * DD], g_b2[(size_t)NT * DD];
__device__ __align__(256) fp16 g_w1a[(size_t)DD * DD], g_w1b[(size_t)DD * DD];
__device__ __align__(256) fp16 g_w2a[(size_t)DD * DD], g_w2b[(size_t)DD * DD];
__device__ float  g_r[NT];
__device__ float  g_c[NT];
__device__ float  g_cz[NT];
__device__ float  g_p[(size_t)CH * NT];
__device__ float2 g_p2[(size_t)CSPLIT * NT];

// ---------------- helpers ----------------
__device__ __forceinline__ uint32_t smem_u32(const void* p) {
    uint32_t a;
    asm("{ .reg .u64 t; cvta.to.shared.u64 t, %1; cvt.u32.u64 %0, t; }"
        : "=r"(a) : "l"(p));
    return a;
}
__device__ __forceinline__ void ldsm4(uint32_t& r0, uint32_t& r1,
                                      uint32_t& r2, uint32_t& r3, uint32_t a) {
    asm volatile("ldmatrix.sync.aligned.m8n8.x4.shared.b16 {%0,%1,%2,%3}, [%4];"
                 : "=r"(r0), "=r"(r1), "=r"(r2), "=r"(r3) : "r"(a));
}
__device__ __forceinline__ void mma16816(float* d, const uint32_t* a,
                                         const uint32_t* b) {
    asm volatile(
        "mma.sync.aligned.m16n8k16.row.col.f32.f16.f16.f32 "
        "{%0,%1,%2,%3}, {%4,%5,%6,%7}, {%8,%9}, {%0,%1,%2,%3};"
        : "+f"(d[0]), "+f"(d[1]), "+f"(d[2]), "+f"(d[3])
        : "r"(a[0]), "r"(a[1]), "r"(a[2]), "r"(a[3]), "r"(b[0]), "r"(b[1]));
}
__device__ __forceinline__ void mbar_init(uint32_t mb) {
    asm volatile("mbarrier.init.shared.b64 [%0], %1;"
                 :: "r"(mb), "r"(1u) : "memory");
}
__device__ __forceinline__ void mbar_inval(uint32_t mb) {
    asm volatile("mbarrier.inval.shared.b64 [%0];" :: "r"(mb) : "memory");
}
__device__ __forceinline__ void mbar_expect(uint32_t mb, uint32_t tx) {
    asm volatile("mbarrier.arrive.expect_tx.shared.b64 _, [%0], %1;"
                 :: "r"(mb), "r"(tx) : "memory");
}
__device__ __forceinline__ void mbar_wait(uint32_t mb, uint32_t phase) {
    asm volatile(
        "{\n\t.reg .pred P;\n\t"
        "WL_%=:\n\t"
        "mbarrier.try_wait.parity.acquire.cta.shared::cta.b64 P, [%0], %1, 0x989680;\n\t"
        "@P bra.uni WD_%=;\n\t"
        "bra.uni WL_%=;\n\t"
        "WD_%=:\n\t}"
        :: "r"(mb), "r"(phase) : "memory");
}
__device__ __forceinline__ void bulk_cp(uint32_t dst, const void* src,
                                        uint32_t bytes, uint32_t mb) {
    asm volatile(
        "cp.async.bulk.shared::cluster.global.mbarrier::complete_tx::bytes "
        "[%0], [%1], %2, [%3];"
        :: "r"(dst), "l"(src), "r"(bytes), "r"(mb) : "memory");
}

__device__ __forceinline__ void split1(float v, fp16& h1, fp16& h2)
{
    h1 = __float2half_rn(v);
    h2 = __float2half_rn(v - __half2float(h1));
}
// swizzled byte offset within a 64B-row tile block (conflict-free for ldsm)
__device__ __forceinline__ uint32_t swz32(uint32_t row, uint32_t colbyte)
{
    return row * 64 + (colbyte ^ (((row >> 1) & 3) << 4));
}

// ================= GEMM geometry =================
#define BKC 32
#define NCHK (DD / BKC)          // 32
#define TBLK 8192                // bytes per 128x32 fp16 block
#define STG (4 * TBLK)           // 32768 bytes per stage
#define NSTG 3
#define MM_SMEM (NSTG * STG + 64)    // 98368 -> 2 CTAs/SM

// ================= split emb -> blocked fp16x2 =================
__global__ void __launch_bounds__(256)
split2(const float* __restrict__ x, fp16* __restrict__ o1,
       fp16* __restrict__ o2)
{
    size_t uid = (size_t)blockIdx.x * 256 + threadIdx.x;  // 16B-granule id
    int row = (int)(uid >> 7);          // 128 granules per row (1024/8)
    int k0 = (int)(uid & 127) * 8;
    const float4* xs = (const float4*)(x + (size_t)row * DD + k0);
    float4 v0 = xs[0], v1 = xs[1];
    float vv[8] = {v0.x, v0.y, v0.z, v0.w, v1.x, v1.y, v1.z, v1.w};
    fp16 h1[8], h2[8];
#pragma unroll
    for (int k = 0; k < 8; k++) split1(vv[k], h1[k], h2[k]);
    size_t blk = ((size_t)(row >> 7) * NCHK + (k0 >> 5)) * TBLK;
    uint32_t ph = swz32(row & 127, (k0 & 31) * 2);
    *(uint4*)((char*)o1 + blk + ph) = *(uint4*)h1;
    *(uint4*)((char*)o2 + blk + ph) = *(uint4*)h2;
}

// ========== transpose + split W [K,N] -> blocked Wt[N,K] ============
__global__ void __launch_bounds__(256)
tsplit(const float* __restrict__ W, fp16* __restrict__ o1,
       fp16* __restrict__ o2)
{
    __shared__ float tile[32][33];
    const int bn = blockIdx.x * 32;
    const int bk = blockIdx.y * 32;
    const int tx = threadIdx.x, ty = threadIdx.y;   // 32 x 8
#pragma unroll
    for (int i = 0; i < 32; i += 8)
        tile[ty + i][tx] = W[(size_t)(bk + ty + i) * DD + bn + tx];
    __syncthreads();
#pragma unroll
    for (int i = 0; i < 32; i += 8) {
        float v = tile[tx][ty + i];
        fp16 h1, h2;
        split1(v, h1, h2);
        int n = bn + ty + i, k = bk + tx;
        size_t blk = ((size_t)(n >> 7) * NCHK + (k >> 5)) * TBLK;
        uint32_t ph = swz32(n & 127, (k & 31) * 2);
        *(fp16*)((char*)o1 + blk + ph) = h1;
        *(fp16*)((char*)o2 + blk + ph) = h2;
    }
}

// ================= mma.sync fp16x3-pair GEMM: acc = A · B^T ================
// CTA tile 128x128, 256 thr (8 warps), warp tile 32x64, BK=32, 3-stage TMA.
enum { EPI_SCORE = 0, EPI_GELU = 1, EPI_BIAS = 2 };

template <int EPI>
__global__ void __launch_bounds__(256, 2)
mma_gemm(const fp16* __restrict__ A1, const fp16* __restrict__ A2,
         const fp16* __restrict__ B1, const fp16* __restrict__ B2,
         const float* __restrict__ bias, float* __restrict__ Cf,
         fp16* __restrict__ O1, fp16* __restrict__ O2, int ldc)
{
    extern __shared__ __align__(128) char sm[];
    const uint32_t sS = smem_u32(sm);
    const uint32_t sMB = sS + NSTG * STG;
    const int tid = threadIdx.x;
    const int wid = tid >> 5, lane = tid & 31;
    const int bm = blockIdx.y * 128, bn = blockIdx.x * 128;
    const int wm = (wid & 3) * 32, wn = (wid >> 2) * 64;

    const char* srcA1 = (const char*)A1 + (size_t)blockIdx.y * NCHK * TBLK;
    const char* srcA2 = (const char*)A2 + (size_t)blockIdx.y * NCHK * TBLK;
    const char* srcB1 = (const char*)B1 + (size_t)blockIdx.x * NCHK * TBLK;
    const char* srcB2 = (const char*)B2 + (size_t)blockIdx.x * NCHK * TBLK;

    float acc[2][8][4];
#pragma unroll
    for (int i = 0; i < 2; i++)
#pragma unroll
        for (int j = 0; j < 8; j++)
#pragma unroll
            for (int k = 0; k < 4; k++) acc[i][j][k] = 0.0f;

    if (tid == 0) {
#pragma unroll
        for (int s = 0; s < NSTG; s++) mbar_init(sMB + s * 8);
    }
    __syncthreads();

    auto arm_load = [&](int ch) {
        int stage = ch % NSTG;
        uint32_t mb = sMB + stage * 8;
        mbar_expect(mb, STG);
        uint32_t so = sS + stage * STG;
        bulk_cp(so + 0 * TBLK, srcA1 + (size_t)ch * TBLK, TBLK, mb);
        bulk_cp(so + 1 * TBLK, srcA2 + (size_t)ch * TBLK, TBLK, mb);
        bulk_cp(so + 2 * TBLK, srcB1 + (size_t)ch * TBLK, TBLK, mb);
        bulk_cp(so + 3 * TBLK, srcB2 + (size_t)ch * TBLK, TBLK, mb);
    };

    if (tid == 0) {
        arm_load(0);
        arm_load(1);
        arm_load(2);
    }

    int stage = 0, phase = 0;
    for (int ch = 0; ch < NCHK; ch++) {
        mbar_wait(sMB + stage * 8, phase);

        const uint32_t so = sS + stage * STG;
        const uint32_t sA1 = so, sA2 = so + TBLK;
        const uint32_t sB1 = so + 2 * TBLK, sB2 = so + 3 * TBLK;

#pragma unroll
        for (int kt = 0; kt < 2; kt++) {
            uint32_t afA[2][2][4];
#pragma unroll
            for (int mt = 0; mt < 2; mt++) {
                uint32_t row = (uint32_t)(wm + mt * 16 + (lane & 15));
                uint32_t ph = swz32(row, kt * 32 + (lane >> 4) * 16);
                ldsm4(afA[0][mt][0], afA[0][mt][1], afA[0][mt][2],
                      afA[0][mt][3], sA1 + ph);
                ldsm4(afA[1][mt][0], afA[1][mt][1], afA[1][mt][2],
                      afA[1][mt][3], sA2 + ph);
            }
#pragma unroll
            for (int np = 0; np < 4; np++) {
                uint32_t rowb = (uint32_t)(wn + np * 16 + (lane & 7) +
                                           ((lane >> 4) << 3));
                uint32_t ph = swz32(rowb, kt * 32 + ((lane >> 3) & 1) * 16);
                uint32_t b1f[4], b2f[4];
                ldsm4(b1f[0], b1f[1], b1f[2], b1f[3], sB1 + ph);
                ldsm4(b2f[0], b2f[1], b2f[2], b2f[3], sB2 + ph);
#pragma unroll
                for (int half = 0; half < 2; half++) {
                    uint32_t bv[2] = {b1f[half * 2], b1f[half * 2 + 1]};
#pragma unroll
                    for (int mt = 0; mt < 2; mt++)
                        mma16816(acc[mt][np * 2 + half], afA[0][mt], bv);
                }
#pragma unroll
                for (int half = 0; half < 2; half++) {
                    uint32_t bv[2] = {b2f[half * 2], b2f[half * 2 + 1]};
#pragma unroll
                    for (int mt = 0; mt < 2; mt++)
                        mma16816(acc[mt][np * 2 + half], afA[0][mt], bv);
                }
#pragma unroll
                for (int half = 0; half < 2; half++) {
                    uint32_t bv[2] = {b1f[half * 2], b1f[half * 2 + 1]};
#pragma unroll
                    for (int mt = 0; mt < 2; mt++)
                        mma16816(acc[mt][np * 2 + half], afA[1][mt], bv);
                }
            }
        }
        __syncthreads();
        // arm ch+3 into the stage just consumed (all warps synced past ch)
        if (ch + 3 < NCHK && tid == 0) arm_load(ch + 3);
        if (++stage == NSTG) { stage = 0; phase ^= 1; }
    }

    // epilogue
#pragma unroll
    for (int mt = 0; mt < 2; mt++) {
#pragma unroll
        for (int nt = 0; nt < 8; nt++) {
            int row = bm + wm + mt * 16 + (lane >> 2);
            int col = bn + wn + nt * 8 + (lane & 3) * 2;
            float* d = acc[mt][nt];
            if (EPI == EPI_SCORE) {
                *(float2*)&Cf[(size_t)row * ldc + col] =
                    make_float2(d[0] * 20.0f, d[1] * 20.0f);
                *(float2*)&Cf[(size_t)(row + 8) * ldc + col] =
                    make_float2(d[2] * 20.0f, d[3] * 20.0f);
            } else {
                float bx = bias[col], by = bias[col + 1];
                float v[4] = {d[0] + bx, d[1] + by, d[2] + bx, d[3] + by};
                if (EPI == EPI_GELU) {
#pragma unroll
                    for (int k = 0; k < 4; k++)
                        v[k] = 0.5f * v[k] *
                               (1.0f + erff(v[k] * 0.70710678118654752f));
                }
#pragma unroll
                for (int h = 0; h < 2; h++) {
                    int rr = row + 8 * h;
                    fp16 s1[2], s2[2];
                    split1(v[2 * h + 0], s1[0], s2[0]);
                    split1(v[2 * h + 1], s1[1], s2[1]);
                    size_t blk = ((size_t)(rr >> 7) * NCHK + (col >> 5)) * TBLK;
                    uint32_t ph = swz32(rr & 127, (col & 31) * 2);
                    *(uint32_t*)((char*)O1 + blk + ph) = *(uint32_t*)s1;
                    *(uint32_t*)((char*)O2 + blk + ph) = *(uint32_t*)s2;
                }
            }
        }
    }
    __syncthreads();
    if (tid == 0) {
#pragma unroll
        for (int s = 0; s < NSTG; s++) mbar_inval(sMB + s * 8);
    }
}

// ================= Sinkhorn (R5-R13 proven) =================
__device__ __forceinline__ void lse_upd(float& m, float& l, float v)
{
    if (v <= m) {
        l += __expf(v - m);
    } else {
        l = fmaf(l, __expf(m - v), 1.0f);
        m = v;
    }
}

__global__ void zero_vec(float* __restrict__ c)
{
    c[blockIdx.x * 256 + threadIdx.x] = 0.0f;
}

__global__ void __launch_bounds__(256)
row_lse_kernel(const float* __restrict__ S, const float* __restrict__ c,
               float* __restrict__ r)
{
    const int row = blockIdx.x;
    const int tid = threadIdx.x;
    const float4* s4 = (const float4*)(S + (size_t)row * NT);
    const float4* c4 = (const float4*)c;

    float m = -INFINITY, l = 0.0f;
    for (int j = tid; j < NT / 4; j += 256) {
        float4 s = s4[j];
        float4 cc = c4[j];
        lse_upd(m, l, s.x - cc.x);
        lse_upd(m, l, s.y - cc.y);
        lse_upd(m, l, s.z - cc.z);
        lse_upd(m, l, s.w - cc.w);
    }

    __shared__ float sm[256], sl[256];
    sm[tid] = m; sl[tid] = l;
    __syncthreads();
    for (int s = 128; s > 0; s >>= 1) {
        if (tid < s) {
            float m2 = sm[tid + s], l2 = sl[tid + s];
            float nm = fmaxf(sm[tid], m2);
            sl[tid] = sl[tid] * __expf(sm[tid] - nm) + l2 * __expf(m2 - nm);
            sm[tid] = nm;
        }
        __syncthreads();
    }
    if (tid == 0) r[row] = sm[0] + __logf(sl[0]);
}

__global__ void __launch_bounds__(256)
col_lse_partial_kernel(const float* __restrict__ S, const float* __restrict__ r,
                       float2* __restrict__ part)
{
    const int j4 = blockIdx.x * blockDim.x + threadIdx.x;
    const int chunk = blockIdx.y;
    const int rowsPer = NT / CSPLIT;
    const int i0 = chunk * rowsPer;

    float m0 = -INFINITY, m1 = -INFINITY, m2 = -INFINITY, m3 = -INFINITY;
    float l0 = 0.f, l1 = 0.f, l2 = 0.f, l3 = 0.f;

    const float4* S4 = (const float4*)S;
    for (int i = i0; i < i0 + rowsPer; i++) {
        float4 s = S4[(size_t)i * (NT / 4) + j4];
        float rv = __ldg(&r[i]);
        lse_upd(m0, l0, s.x - rv);
        lse_upd(m1, l1, s.y - rv);
        lse_upd(m2, l2, s.z - rv);
        lse_upd(m3, l3, s.w - rv);
    }
    int j = j4 * 4;
    float2* p = part + (size_t)chunk * NT + j;
    p[0] = make_float2(m0, l0);
    p[1] = make_float2(m1, l1);
    p[2] = make_float2(m2, l2);
    p[3] = make_float2(m3, l3);
}

__global__ void __launch_bounds__(256)
col_lse_combine_kernel(const float2* __restrict__ part, float* __restrict__ c)
{
    const int j = blockIdx.x * blockDim.x + threadIdx.x;
    float m = -INFINITY, l = 0.0f;
    for (int k = 0; k < CSPLIT; k++) {
        float2 p = part[(size_t)k * NT + j];
        float nm = fmaxf(m, p.x);
        l = l * __expf(m - nm) + p.y * __expf(p.x - nm);
        m = nm;
    }
    c[j] = m + __logf(l);
}

__device__ __forceinline__ float blk_sum(float x, float* sb, int tid)
{
#pragma unroll
    for (int o = 16; o; o >>= 1) x += __shfl_down_sync(0xffffffffu, x, o);
    if ((tid & 31) == 0) sb[tid >> 5] = x;
    __syncthreads();
    if (tid < 32) {
        float y = (tid < 8) ? sb[tid] : 0.0f;
#pragma unroll
        for (int o = 4; o; o >>= 1) y += __shfl_down_sync(0xffffffffu, y, o);
        if (tid == 0) sb[32] = y;
    }
    __syncthreads();
    float r = sb[32];
    __syncthreads();
    return r;
}

__global__ void __launch_bounds__(256)
sink_fast(const float* __restrict__ S, float* __restrict__ r,
          const float* __restrict__ c, float* __restrict__ part)
{
    __shared__ float cc[NT];
    __shared__ float sb[40];
    const int tid = threadIdx.x, chunk = blockIdx.x;

    for (int k = tid; k < NT / 4; k += 256)
        ((float4*)cc)[k] = ((const float4*)c)[k];
    __syncthreads();

    float acc[32];
#pragma unroll
    for (int k = 0; k < 32; k++) acc[k] = 0.0f;

    for (int i = chunk * RPC; i < chunk * RPC + RPC; i++) {
        const float4* S4 = (const float4*)(S + (size_t)i * NT);
        const float rr = r[i];
        float4 e[8];
        float dot = 0.0f;
#pragma unroll
        for (int q = 0; q < 8; q++) {
            float4 s = S4[tid + 256 * q];
            float4 cv = *(const float4*)&cc[4 * (tid + 256 * q)];
            e[q].x = __expf(s.x - cv.x - rr);
            e[q].y = __expf(s.y - cv.y - rr);
            e[q].z = __expf(s.z - cv.z - rr);
            e[q].w = __expf(s.w - cv.w - rr);
            dot += (e[q].x + e[q].y) + (e[q].z + e[q].w);
        }
        dot = blk_sum(dot, sb, tid);
        float w = __fdividef(1.0f, dot);
        if (tid == 0) r[i] = rr + __logf(dot);
#pragma unroll
        for (int q = 0; q < 8; q++) {
            acc[4 * q + 0] = fmaf(e[q].x, w, acc[4 * q + 0]);
            acc[4 * q + 1] = fmaf(e[q].y, w, acc[4 * q + 1]);
            acc[4 * q + 2] = fmaf(e[q].z, w, acc[4 * q + 2]);
            acc[4 * q + 3] = fmaf(e[q].w, w, acc[4 * q + 3]);
        }
    }
    float* pp = part + (size_t)chunk * NT;
#pragma unroll
    for (int q = 0; q < 8; q++) {
        int j = 4 * (tid + 256 * q);
        *(float4*)&pp[j] = make_float4(acc[4 * q + 0], acc[4 * q + 1],
                                       acc[4 * q + 2], acc[4 * q + 3]);
    }
}

__global__ void __launch_bounds__(256)
comb_add(const float* __restrict__ part, float* __restrict__ c)
{
    const int j = blockIdx.x * 256 + threadIdx.x;
    float s = 0.0f;
    for (int k = 0; k < CH; k++) s += part[(size_t)k * NT + j];
    c[j] += __logf(s);
}

__global__ void __launch_bounds__(256)
final_exp_kernel(float* __restrict__ S, const float* __restrict__ r,
                 const float* __restrict__ c)
{
    size_t idx = (size_t)blockIdx.x * blockDim.x + threadIdx.x;
    int row = (int)(idx >> 11);
    int j4 = (int)(idx & 2047);
    float4 s = ((const float4*)S)[idx];
    float rv = r[row];
    float4 cc = ((const float4*)c)[j4];
    s.x = __expf(s.x - rv - cc.x);
    s.y = __expf(s.y - rv - cc.y);
    s.z = __expf(s.z - rv - cc.z);
    s.w = __expf(s.w - rv - cc.w);
    ((float4*)S)[idx] = s;
}

// ---------------- launch ----------------
extern "C" void kernel_launch(void* const* d_in, const int* in_sizes, int n_in,
                              void* d_out, int out_size)
{
    const float* emb_a = (const float*)d_in[0];
    const float* emb_b = (const float*)d_in[1];
    const float* W1    = (const float*)d_in[2];
    const float* b1    = (const float*)d_in[3];
    const float* W2    = (const float*)d_in[4];
    const float* b2    = (const float*)d_in[5];
    float* out = (float*)d_out;

    float *r, *c, *cz, *p;
    float2* p2;
    fp16 *e1, *e2, *t1, *t2, *a1, *a2, *bb1, *bb2;
    fp16 *w1a, *w1b, *w2a, *w2b;
    cudaGetSymbolAddress((void**)&r, g_r);
    cudaGetSymbolAddress((void**)&c, g_c);
    cudaGetSymbolAddress((void**)&cz, g_cz);
    cudaGetSymbolAddress((void**)&p, g_p);
    cudaGetSymbolAddress((void**)&p2, g_p2);
    cudaGetSymbolAddress((void**)&e1, g_e1);
    cudaGetSymbolAddress((void**)&e2, g_e2);
    cudaGetSymbolAddress((void**)&t1, g_t1);
    cudaGetSymbolAddress((void**)&t2, g_t2);
    cudaGetSymbolAddress((void**)&a1, g_a1);
    cudaGetSymbolAddress((void**)&a2, g_a2);
    cudaGetSymbolAddress((void**)&bb1, g_b1);
    cudaGetSymbolAddress((void**)&bb2, g_b2);
    cudaGetSymbolAddress((void**)&w1a, g_w1a);
    cudaGetSymbolAddress((void**)&w1b, g_w1b);
    cudaGetSymbolAddress((void**)&w2a, g_w2a);
    cudaGetSymbolAddress((void**)&w2b, g_w2b);

    cudaFuncSetAttribute(mma_gemm<EPI_SCORE>,
                         cudaFuncAttributeMaxDynamicSharedMemorySize, MM_SMEM);
    cudaFuncSetAttribute(mma_gemm<EPI_GELU>,
                         cudaFuncAttributeMaxDynamicSharedMemorySize, MM_SMEM);
    cudaFuncSetAttribute(mma_gemm<EPI_BIAS>,
                         cudaFuncAttributeMaxDynamicSharedMemorySize, MM_SMEM);

    dim3 blk(256);
    dim3 tblk(32, 8);
    dim3 tgrid(DD / 32, DD / 32);
    dim3 grid_mlp(DD / 128, NT / 128);   // (8, 64)
    dim3 grid_big(NT / 128, NT / 128);   // (64, 64)
    unsigned nsplit = (unsigned)((size_t)NT * DD / 8 / 256);   // 4096

    // weight transpose + split (once)
    tsplit<<<tgrid, tblk>>>(W1, w1a, w1b);
    tsplit<<<tgrid, tblk>>>(W2, w2a, w2b);

    // ---- projection of emb_a ----
    split2<<<nsplit, blk>>>(emb_a, e1, e2);
    mma_gemm<EPI_GELU><<<grid_mlp, blk, MM_SMEM>>>(
        e1, e2, w1a, w1b, b1, nullptr, t1, t2, DD);
    mma_gemm<EPI_BIAS><<<grid_mlp, blk, MM_SMEM>>>(
        t1, t2, w2a, w2b, b2, nullptr, a1, a2, DD);

    // ---- projection of emb_b ----
    split2<<<nsplit, blk>>>(emb_b, e1, e2);
    mma_gemm<EPI_GELU><<<grid_mlp, blk, MM_SMEM>>>(
        e1, e2, w1a, w1b, b1, nullptr, t1, t2, DD);
    mma_gemm<EPI_BIAS><<<grid_mlp, blk, MM_SMEM>>>(
        t1, t2, w2a, w2b, b2, nullptr, bb1, bb2, DD);

    // ---- scores = (a @ b^T) * 20 ----
    mma_gemm<EPI_SCORE><<<grid_big, blk, MM_SMEM>>>(
        a1, a2, bb1, bb2, nullptr, out, nullptr, nullptr, NT);

    // ---- Sinkhorn iteration 1 (exact, overflow-safe) ----
    zero_vec<<<NT / 256, blk>>>(cz);
    row_lse_kernel<<<NT, blk>>>(out, cz, r);
    col_lse_partial_kernel<<<dim3((NT / 4) / 256, CSPLIT), blk>>>(out, r, p2);
    col_lse_combine_kernel<<<NT / 256, blk>>>(p2, c);

    // ---- iterations 2..20: fused fast path ----
    for (int it = 0; it < 19; it++) {
        sink_fast<<<CH, blk>>>(out, r, c, p);
        comb_add<<<NT / 256, blk>>>(p, c);
    }

    final_exp_kernel<<<(unsigned)((size_t)NT * NT / 4 / 256), blk>>>(out, r, c);
}

// round 16
// speedup vs baseline: 1.0529x; 1.0211x over previous
#include <cuda_runtime.h>
#include <cuda_fp16.h>
#include <math.h>
#include <stdint.h>

#define NT 8192
#define DD 1024
#define CSPLIT 128        // iter-1 column-partial chunks
#define CH 512            // fast-iter row chunks
#define RPC (NT / CH)     // 16 rows per chunk

typedef __half fp16;

// ---------------- scratch (device globals; blocked operand layout) ---------
// All operands: [blk=row/128][ch=32][128 rows x 32 fp16 (64B rows), swizzled]
// e/t/s buffers are stacked: rows 0..8191 = emb_a path, 8192..16383 = emb_b.
__device__ __align__(256) fp16 g_e1[(size_t)2 * NT * DD], g_e2[(size_t)2 * NT * DD];
__device__ __align__(256) fp16 g_t1[(size_t)2 * NT * DD], g_t2[(size_t)2 * NT * DD];
__device__ __align__(256) fp16 g_s1[(size_t)2 * NT * DD], g_s2[(size_t)2 * NT * DD];
__device__ __align__(256) fp16 g_w1a[(size_t)DD * DD], g_w1b[(size_t)DD * DD];
__device__ __align__(256) fp16 g_w2a[(size_t)DD * DD], g_w2b[(size_t)DD * DD];
__device__ float  g_r[NT];
__device__ float  g_c[NT];
__device__ float  g_cz[NT];
__device__ float  g_p[(size_t)CH * NT];
__device__ float2 g_p2[(size_t)CSPLIT * NT];

// ---------------- helpers ----------------
__device__ __forceinline__ uint32_t smem_u32(const void* p) {
    uint32_t a;
    asm("{ .reg .u64 t; cvta.to.shared.u64 t, %1; cvt.u32.u64 %0, t; }"
        : "=r"(a) : "l"(p));
    return a;
}
__device__ __forceinline__ void ldsm4(uint32_t& r0, uint32_t& r1,
                                      uint32_t& r2, uint32_t& r3, uint32_t a) {
    asm volatile("ldmatrix.sync.aligned.m8n8.x4.shared.b16 {%0,%1,%2,%3}, [%4];"
                 : "=r"(r0), "=r"(r1), "=r"(r2), "=r"(r3) : "r"(a));
}
__device__ __forceinline__ void mma16816(float* d, const uint32_t* a,
                                         const uint32_t* b) {
    asm volatile(
        "mma.sync.aligned.m16n8k16.row.col.f32.f16.f16.f32 "
        "{%0,%1,%2,%3}, {%4,%5,%6,%7}, {%8,%9}, {%0,%1,%2,%3};"
        : "+f"(d[0]), "+f"(d[1]), "+f"(d[2]), "+f"(d[3])
        : "r"(a[0]), "r"(a[1]), "r"(a[2]), "r"(a[3]), "r"(b[0]), "r"(b[1]));
}
__device__ __forceinline__ void mbar_init_cnt(uint32_t mb, uint32_t n) {
    asm volatile("mbarrier.init.shared.b64 [%0], %1;"
                 :: "r"(mb), "r"(n) : "memory");
}
__device__ __forceinline__ void mbar_inval(uint32_t mb) {
    asm volatile("mbarrier.inval.shared.b64 [%0];" :: "r"(mb) : "memory");
}
__device__ __forceinline__ void mbar_expect(uint32_t mb, uint32_t tx) {
    asm volatile("mbarrier.arrive.expect_tx.shared.b64 _, [%0], %1;"
                 :: "r"(mb), "r"(tx) : "memory");
}
__device__ __forceinline__ void mbar_arrive(uint32_t mb) {
    asm volatile("mbarrier.arrive.shared.b64 _, [%0];" :: "r"(mb) : "memory");
}
__device__ __forceinline__ void mbar_wait(uint32_t mb, uint32_t phase) {
    asm volatile(
        "{\n\t.reg .pred P;\n\t"
        "WL_%=:\n\t"
        "mbarrier.try_wait.parity.acquire.cta.shared::cta.b64 P, [%0], %1, 0x989680;\n\t"
        "@P bra.uni WD_%=;\n\t"
        "bra.uni WL_%=;\n\t"
        "WD_%=:\n\t}"
        :: "r"(mb), "r"(phase) : "memory");
}
__device__ __forceinline__ void bulk_cp(uint32_t dst, const void* src,
                                        uint32_t bytes, uint32_t mb) {
    asm volatile(
        "cp.async.bulk.shared::cluster.global.mbarrier::complete_tx::bytes "
        "[%0], [%1], %2, [%3];"
        :: "r"(dst), "l"(src), "r"(bytes), "r"(mb) : "memory");
}

__device__ __forceinline__ void split1(float v, fp16& h1, fp16& h2)
{
    h1 = __float2half_rn(v);
    h2 = __float2half_rn(v - __half2float(h1));
}
// swizzled byte offset within a 64B-row tile block (conflict-free for ldsm)
__device__ __forceinline__ uint32_t swz32(uint32_t row, uint32_t colbyte)
{
    return row * 64 + (colbyte ^ (((row >> 1) & 3) << 4));
}

// ================= GEMM geometry =================
#define BKC 32
#define NCHK (DD / BKC)          // 32
#define TBLK 8192                // bytes per 128x32 fp16 block
#define STG (4 * TBLK)           // 32768 bytes per stage
#define NSTG 3
#define MM_SMEM (NSTG * STG + 128)   // ~98 KB -> 2 CTAs/SM

// ======= split stacked [emb_a; emb_b] -> blocked fp16x2 =======
__global__ void __launch_bounds__(256)
split2(const float* __restrict__ xa, const float* __restrict__ xb,
       fp16* __restrict__ o1, fp16* __restrict__ o2)
{
    size_t uid = (size_t)blockIdx.x * 256 + threadIdx.x;  // 16B-granule id
    int row = (int)(uid >> 7);          // 0..16383
    int k0 = (int)(uid & 127) * 8;
    const float* src = (row < NT) ? (xa + (size_t)row * DD)
                                  : (xb + (size_t)(row - NT) * DD);
    const float4* xs = (const float4*)(src + k0);
    float4 v0 = xs[0], v1 = xs[1];
    float vv[8] = {v0.x, v0.y, v0.z, v0.w, v1.x, v1.y, v1.z, v1.w};
    fp16 h1[8], h2[8];
#pragma unroll
    for (int k = 0; k < 8; k++) split1(vv[k], h1[k], h2[k]);
    size_t blk = ((size_t)(row >> 7) * NCHK + (k0 >> 5)) * TBLK;
    uint32_t ph = swz32(row & 127, (k0 & 31) * 2);
    *(uint4*)((char*)o1 + blk + ph) = *(uint4*)h1;
    *(uint4*)((char*)o2 + blk + ph) = *(uint4*)h2;
}

// ========== transpose + split W [K,N] -> blocked Wt[N,K] ============
__global__ void __launch_bounds__(256)
tsplit(const float* __restrict__ W, fp16* __restrict__ o1,
       fp16* __restrict__ o2)
{
    __shared__ float tile[32][33];
    const int bn = blockIdx.x * 32;
    const int bk = blockIdx.y * 32;
    const int tx = threadIdx.x, ty = threadIdx.y;   // 32 x 8
#pragma unroll
    for (int i = 0; i < 32; i += 8)
        tile[ty + i][tx] = W[(size_t)(bk + ty + i) * DD + bn + tx];
    __syncthreads();
#pragma unroll
    for (int i = 0; i < 32; i += 8) {
        float v = tile[tx][ty + i];
        fp16 h1, h2;
        split1(v, h1, h2);
        int n = bn + ty + i, k = bk + tx;
        size_t blk = ((size_t)(n >> 7) * NCHK + (k >> 5)) * TBLK;
        uint32_t ph = swz32(n & 127, (k & 31) * 2);
        *(fp16*)((char*)o1 + blk + ph) = h1;
        *(fp16*)((char*)o2 + blk + ph) = h2;
    }
}

// ================= mma.sync fp16x3-pair GEMM: acc = A · B^T ================
// CTA tile 128x128, 8 warps, warp tile 32x64, BK=32, 3-stage TMA pipeline
// with full/empty mbarriers (no block syncs in mainloop).
enum { EPI_SCORE = 0, EPI_GELU = 1, EPI_BIAS = 2 };

template <int EPI>
__global__ void __launch_bounds__(256, 2)
mma_gemm(const fp16* __restrict__ A1, const fp16* __restrict__ A2,
         const fp16* __restrict__ B1, const fp16* __restrict__ B2,
         const float* __restrict__ bias, float* __restrict__ Cf,
         fp16* __restrict__ O1, fp16* __restrict__ O2, int ldc)
{
    extern __shared__ __align__(128) char sm[];
    const uint32_t sS = smem_u32(sm);
    const uint32_t sFull = sS + NSTG * STG;       // full[0..2]
    const uint32_t sEmpty = sFull + NSTG * 8;     // empty[0..2]
    const int tid = threadIdx.x;
    const int wid = tid >> 5, lane = tid & 31;
    const int bm = blockIdx.y * 128, bn = blockIdx.x * 128;
    const int wm = (wid & 3) * 32, wn = (wid >> 2) * 64;

    const char* srcA1 = (const char*)A1 + (size_t)blockIdx.y * NCHK * TBLK;
    const char* srcA2 = (const char*)A2 + (size_t)blockIdx.y * NCHK * TBLK;
    const char* srcB1 = (const char*)B1 + (size_t)blockIdx.x * NCHK * TBLK;
    const char* srcB2 = (const char*)B2 + (size_t)blockIdx.x * NCHK * TBLK;

    float acc[2][8][4];
#pragma unroll
    for (int i = 0; i < 2; i++)
#pragma unroll
        for (int j = 0; j < 8; j++)
#pragma unroll
            for (int k = 0; k < 4; k++) acc[i][j][k] = 0.0f;

    if (tid == 0) {
#pragma unroll
        for (int s = 0; s < NSTG; s++) {
            mbar_init_cnt(sFull + s * 8, 1);
            mbar_init_cnt(sEmpty + s * 8, 8);   // one arrive per warp
        }
    }
    __syncthreads();

    auto arm_load = [&](int ch) {
        int stage = ch % NSTG;
        uint32_t mb = sFull + stage * 8;
        mbar_expect(mb, STG);
        uint32_t so = sS + stage * STG;
        bulk_cp(so + 0 * TBLK, srcA1 + (size_t)ch * TBLK, TBLK, mb);
        bulk_cp(so + 1 * TBLK, srcA2 + (size_t)ch * TBLK, TBLK, mb);
        bulk_cp(so + 2 * TBLK, srcB1 + (size_t)ch * TBLK, TBLK, mb);
        bulk_cp(so + 3 * TBLK, srcB2 + (size_t)ch * TBLK, TBLK, mb);
    };

    if (tid == 0) {
        arm_load(0);
        arm_load(1);
        arm_load(2);
    }

    int stage = 0, phase = 0;
    for (int ch = 0; ch < NCHK; ch++) {
        mbar_wait(sFull + stage * 8, phase);

        const uint32_t so = sS + stage * STG;
        const uint32_t sA1 = so, sA2 = so + TBLK;
        const uint32_t sB1 = so + 2 * TBLK, sB2 = so + 3 * TBLK;

#pragma unroll
        for (int kt = 0; kt < 2; kt++) {
            uint32_t afA[2][2][4];
#pragma unroll
            for (int mt = 0; mt < 2; mt++) {
                uint32_t row = (uint32_t)(wm + mt * 16 + (lane & 15));
                uint32_t ph = swz32(row, kt * 32 + (lane >> 4) * 16);
                ldsm4(afA[0][mt][0], afA[0][mt][1], afA[0][mt][2],
                      afA[0][mt][3], sA1 + ph);
                ldsm4(afA[1][mt][0], afA[1][mt][1], afA[1][mt][2],
                      afA[1][mt][3], sA2 + ph);
            }
#pragma unroll
            for (int np = 0; np < 4; np++) {
                uint32_t rowb = (uint32_t)(wn + np * 16 + (lane & 7) +
                                           ((lane >> 4) << 3));
                uint32_t ph = swz32(rowb, kt * 32 + ((lane >> 3) & 1) * 16);
                uint32_t b1f[4], b2f[4];
                ldsm4(b1f[0], b1f[1], b1f[2], b1f[3], sB1 + ph);
                ldsm4(b2f[0], b2f[1], b2f[2], b2f[3], sB2 + ph);
#pragma unroll
                for (int half = 0; half < 2; half++) {
                    uint32_t bv[2] = {b1f[half * 2], b1f[half * 2 + 1]};
#pragma unroll
                    for (int mt = 0; mt < 2; mt++)
                        mma16816(acc[mt][np * 2 + half], afA[0][mt], bv);
                }
#pragma unroll
                for (int half = 0; half < 2; half++) {
                    uint32_t bv[2] = {b2f[half * 2], b2f[half * 2 + 1]};
#pragma unroll
                    for (int mt = 0; mt < 2; mt++)
                        mma16816(acc[mt][np * 2 + half], afA[0][mt], bv);
                }
#pragma unroll
                for (int half = 0; half < 2; half++) {
                    uint32_t bv[2] = {b1f[half * 2], b1f[half * 2 + 1]};
#pragma unroll
                    for (int mt = 0; mt < 2; mt++)
                        mma16816(acc[mt][np * 2 + half], afA[1][mt], bv);
                }
            }
        }
        // consumer done with this stage
        if (lane == 0) mbar_arrive(sEmpty + stage * 8);
        // producer: wait all 8 warps done, then refill this stage with ch+3
        if (tid == 0 && ch + NSTG < NCHK) {
            mbar_wait(sEmpty + stage * 8, phase);
            arm_load(ch + NSTG);
        }
        if (++stage == NSTG) { stage = 0; phase ^= 1; }
    }

    // epilogue
#pragma unroll
    for (int mt = 0; mt < 2; mt++) {
#pragma unroll
        for (int nt = 0; nt < 8; nt++) {
            int row = bm + wm + mt * 16 + (lane >> 2);
            int col = bn + wn + nt * 8 + (lane & 3) * 2;
            float* d = acc[mt][nt];
            if (EPI == EPI_SCORE) {
                *(float2*)&Cf[(size_t)row * ldc + col] =
                    make_float2(d[0] * 20.0f, d[1] * 20.0f);
                *(float2*)&Cf[(size_t)(row + 8) * ldc + col] =
                    make_float2(d[2] * 20.0f, d[3] * 20.0f);
            } else {
                float bx = bias[col], by = bias[col + 1];
                float v[4] = {d[0] + bx, d[1] + by, d[2] + bx, d[3] + by};
                if (EPI == EPI_GELU) {
#pragma unroll
                    for (int k = 0; k < 4; k++)
                        v[k] = 0.5f * v[k] *
                               (1.0f + erff(v[k] * 0.70710678118654752f));
                }
#pragma unroll
                for (int h = 0; h < 2; h++) {
                    int rr = row + 8 * h;
                    fp16 s1[2], s2[2];
                    split1(v[2 * h + 0], s1[0], s2[0]);
                    split1(v[2 * h + 1], s1[1], s2[1]);
                    size_t blk = ((size_t)(rr >> 7) * NCHK + (col >> 5)) * TBLK;
                    uint32_t ph = swz32(rr & 127, (col & 31) * 2);
                    *(uint32_t*)((char*)O1 + blk + ph) = *(uint32_t*)s1;
                    *(uint32_t*)((char*)O2 + blk + ph) = *(uint32_t*)s2;
                }
            }
        }
    }
    __syncthreads();
    if (tid == 0) {
#pragma unroll
        for (int s = 0; s < NSTG; s++) {
            mbar_inval(sFull + s * 8);
            mbar_inval(sEmpty + s * 8);
        }
    }
}

// ================= Sinkhorn (R5-R15 proven) =================
__device__ __forceinline__ void lse_upd(float& m, float& l, float v)
{
    if (v <= m) {
        l += __expf(v - m);
    } else {
        l = fmaf(l, __expf(m - v), 1.0f);
        m = v;
    }
}

__global__ void zero_vec(float* __restrict__ c)
{
    c[blockIdx.x * 256 + threadIdx.x] = 0.0f;
}

__global__ void __launch_bounds__(256)
row_lse_kernel(const float* __restrict__ S, const float* __restrict__ c,
               float* __restrict__ r)
{
    const int row = blockIdx.x;
    const int tid = threadIdx.x;
    const float4* s4 = (const float4*)(S + (size_t)row * NT);
    const float4* c4 = (const float4*)c;

    float m = -INFINITY, l = 0.0f;
    for (int j = tid; j < NT / 4; j += 256) {
        float4 s = s4[j];
        float4 cc = c4[j];
        lse_upd(m, l, s.x - cc.x);
        lse_upd(m, l, s.y - cc.y);
        lse_upd(m, l, s.z - cc.z);
        lse_upd(m, l, s.w - cc.w);
    }

    __shared__ float sm[256], sl[256];
    sm[tid] = m; sl[tid] = l;
    __syncthreads();
    for (int s = 128; s > 0; s >>= 1) {
        if (tid < s) {
            float m2 = sm[tid + s], l2 = sl[tid + s];
            float nm = fmaxf(sm[tid], m2);
            sl[tid] = sl[tid] * __expf(sm[tid] - nm) + l2 * __expf(m2 - nm);
            sm[tid] = nm;
        }
        __syncthreads();
    }
    if (tid == 0) r[row] = sm[0] + __logf(sl[0]);
}

__global__ void __launch_bounds__(256)
col_lse_partial_kernel(const float* __restrict__ S, const float* __restrict__ r,
                       float2* __restrict__ part)
{
    const int j4 = blockIdx.x * blockDim.x + threadIdx.x;
    const int chunk = blockIdx.y;
    const int rowsPer = NT / CSPLIT;
    const int i0 = chunk * rowsPer;

    float m0 = -INFINITY, m1 = -INFINITY, m2 = -INFINITY, m3 = -INFINITY;
    float l0 = 0.f, l1 = 0.f, l2 = 0.f, l3 = 0.f;

    const float4* S4 = (const float4*)S;
    for (int i = i0; i < i0 + rowsPer; i++) {
        float4 s = S4[(size_t)i * (NT / 4) + j4];
        float rv = __ldg(&r[i]);
        lse_upd(m0, l0, s.x - rv);
        lse_upd(m1, l1, s.y - rv);
        lse_upd(m2, l2, s.z - rv);
        lse_upd(m3, l3, s.w - rv);
    }
    int j = j4 * 4;
    float2* p = part + (size_t)chunk * NT + j;
    p[0] = make_float2(m0, l0);
    p[1] = make_float2(m1, l1);
    p[2] = make_float2(m2, l2);
    p[3] = make_float2(m3, l3);
}

__global__ void __launch_bounds__(256)
col_lse_combine_kernel(const float2* __restrict__ part, float* __restrict__ c)
{
    const int j = blockIdx.x * blockDim.x + threadIdx.x;
    float m = -INFINITY, l = 0.0f;
    for (int k = 0; k < CSPLIT; k++) {
        float2 p = part[(size_t)k * NT + j];
        float nm = fmaxf(m, p.x);
        l = l * __expf(m - nm) + p.y * __expf(p.x - nm);
        m = nm;
    }
    c[j] = m + __logf(l);
}

__device__ __forceinline__ float blk_sum(float x, float* sb, int tid)
{
#pragma unroll
    for (int o = 16; o; o >>= 1) x += __shfl_down_sync(0xffffffffu, x, o);
    if ((tid & 31) == 0) sb[tid >> 5] = x;
    __syncthreads();
    if (tid < 32) {
        float y = (tid < 8) ? sb[tid] : 0.0f;
#pragma unroll
        for (int o = 4; o; o >>= 1) y += __shfl_down_sync(0xffffffffu, y, o);
        if (tid == 0) sb[32] = y;
    }
    __syncthreads();
    float r = sb[32];
    __syncthreads();
    return r;
}

__global__ void __launch_bounds__(256)
sink_fast(const float* __restrict__ S, float* __restrict__ r,
          const float* __restrict__ c, float* __restrict__ part)
{
    __shared__ float cc[NT];
    __shared__ float sb[40];
    const int tid = threadIdx.x, chunk = blockIdx.x;

    for (int k = tid; k < NT / 4; k += 256)
        ((float4*)cc)[k] = ((const float4*)c)[k];
    __syncthreads();

    float acc[32];
#pragma unroll
    for (int k = 0; k < 32; k++) acc[k] = 0.0f;

    for (int i = chunk * RPC; i < chunk * RPC + RPC; i++) {
        const float4* S4 = (const float4*)(S + (size_t)i * NT);
        const float rr = r[i];
        float4 e[8];
        float dot = 0.0f;
#pragma unroll
        for (int q = 0; q < 8; q++) {
            float4 s = S4[tid + 256 * q];
            float4 cv = *(const float4*)&cc[4 * (tid + 256 * q)];
            e[q].x = __expf(s.x - cv.x - rr);
            e[q].y = __expf(s.y - cv.y - rr);
            e[q].z = __expf(s.z - cv.z - rr);
            e[q].w = __expf(s.w - cv.w - rr);
            dot += (e[q].x + e[q].y) + (e[q].z + e[q].w);
        }
        dot = blk_sum(dot, sb, tid);
        float w = __fdividef(1.0f, dot);
        if (tid == 0) r[i] = rr + __logf(dot);
#pragma unroll
        for (int q = 0; q < 8; q++) {
            acc[4 * q + 0] = fmaf(e[q].x, w, acc[4 * q + 0]);
            acc[4 * q + 1] = fmaf(e[q].y, w, acc[4 * q + 1]);
            acc[4 * q + 2] = fmaf(e[q].z, w, acc[4 * q + 2]);
            acc[4 * q + 3] = fmaf(e[q].w, w, acc[4 * q + 3]);
        }
    }
    float* pp = part + (size_t)chunk * NT;
#pragma unroll
    for (int q = 0; q < 8; q++) {
        int j = 4 * (tid + 256 * q);
        *(float4*)&pp[j] = make_float4(acc[4 * q + 0], acc[4 * q + 1],
                                       acc[4 * q + 2], acc[4 * q + 3]);
    }
}

__global__ void __launch_bounds__(256)
comb_add(const float* __restrict__ part, float* __restrict__ c)
{
    const int j = blockIdx.x * 256 + threadIdx.x;
    float s = 0.0f;
    for (int k = 0; k < CH; k++) s += part[(size_t)k * NT + j];
    c[j] += __logf(s);
}

__global__ void __launch_bounds__(256)
final_exp_kernel(float* __restrict__ S, const float* __restrict__ r,
                 const float* __restrict__ c)
{
    size_t idx = (size_t)blockIdx.x * blockDim.x + threadIdx.x;
    int row = (int)(idx >> 11);
    int j4 = (int)(idx & 2047);
    float4 s = ((const float4*)S)[idx];
    float rv = r[row];
    float4 cc = ((const float4*)c)[j4];
    s.x = __expf(s.x - rv - cc.x);
    s.y = __expf(s.y - rv - cc.y);
    s.z = __expf(s.z - rv - cc.z);
    s.w = __expf(s.w - rv - cc.w);
    ((float4*)S)[idx] = s;
}

// ---------------- launch ----------------
extern "C" void kernel_launch(void* const* d_in, const int* in_sizes, int n_in,
                              void* d_out, int out_size)
{
    const float* emb_a = (const float*)d_in[0];
    const float* emb_b = (const float*)d_in[1];
    const float* W1    = (const float*)d_in[2];
    const float* b1    = (const float*)d_in[3];
    const float* W2    = (const float*)d_in[4];
    const float* b2    = (const float*)d_in[5];
    float* out = (float*)d_out;

    float *r, *c, *cz, *p;
    float2* p2;
    fp16 *e1, *e2, *t1, *t2, *s1, *s2;
    fp16 *w1a, *w1b, *w2a, *w2b;
    cudaGetSymbolAddress((void**)&r, g_r);
    cudaGetSymbolAddress((void**)&c, g_c);
    cudaGetSymbolAddress((void**)&cz, g_cz);
    cudaGetSymbolAddress((void**)&p, g_p);
    cudaGetSymbolAddress((void**)&p2, g_p2);
    cudaGetSymbolAddress((void**)&e1, g_e1);
    cudaGetSymbolAddress((void**)&e2, g_e2);
    cudaGetSymbolAddress((void**)&t1, g_t1);
    cudaGetSymbolAddress((void**)&t2, g_t2);
    cudaGetSymbolAddress((void**)&s1, g_s1);
    cudaGetSymbolAddress((void**)&s2, g_s2);
    cudaGetSymbolAddress((void**)&w1a, g_w1a);
    cudaGetSymbolAddress((void**)&w1b, g_w1b);
    cudaGetSymbolAddress((void**)&w2a, g_w2a);
    cudaGetSymbolAddress((void**)&w2b, g_w2b);

    // stacked buffer halves: a = rows 0..8191, b = rows 8192..16383
    fp16* a1 = s1;
    fp16* a2 = s2;
    fp16* bb1 = s1 + (size_t)NT * DD;
    fp16* bb2 = s2 + (size_t)NT * DD;

    cudaFuncSetAttribute(mma_gemm<EPI_SCORE>,
                         cudaFuncAttributeMaxDynamicSharedMemorySize, MM_SMEM);
    cudaFuncSetAttribute(mma_gemm<EPI_GELU>,
                         cudaFuncAttributeMaxDynamicSharedMemorySize, MM_SMEM);
    cudaFuncSetAttribute(mma_gemm<EPI_BIAS>,
                         cudaFuncAttributeMaxDynamicSharedMemorySize, MM_SMEM);

    dim3 blk(256);
    dim3 tblk(32, 8);
    dim3 tgrid(DD / 32, DD / 32);
    dim3 grid_mlp(DD / 128, 2 * NT / 128);   // (8, 128) stacked
    dim3 grid_big(NT / 128, NT / 128);       // (64, 64)
    unsigned nsplit = (unsigned)((size_t)2 * NT * DD / 8 / 256);   // 8192

    // weight transpose + split (once)
    tsplit<<<tgrid, tblk>>>(W1, w1a, w1b);
    tsplit<<<tgrid, tblk>>>(W2, w2a, w2b);

    // ---- stacked projections: [a;b] = MLP(MLP1([emb_a;emb_b])) ----
    split2<<<nsplit, blk>>>(emb_a, emb_b, e1, e2);
    mma_gemm<EPI_GELU><<<grid_mlp, blk, MM_SMEM>>>(
        e1, e2, w1a, w1b, b1, nullptr, t1, t2, DD);
    mma_gemm<EPI_BIAS><<<grid_mlp, blk, MM_SMEM>>>(
        t1, t2, w2a, w2b, b2, nullptr, s1, s2, DD);

    // ---- scores = (a @ b^T) * 20 ----
    mma_gemm<EPI_SCORE><<<grid_big, blk, MM_SMEM>>>(
        a1, a2, bb1, bb2, nullptr, out, nullptr, nullptr, NT);

    // ---- Sinkhorn iteration 1 (exact, overflow-safe) ----
    zero_vec<<<NT / 256, blk>>>(cz);
    row_lse_kernel<<<NT, blk>>>(out, cz, r);
    col_lse_partial_kernel<<<dim3((NT / 4) / 256, CSPLIT), blk>>>(out, r, p2);
    col_lse_combine_kernel<<<NT / 256, blk>>>(p2, c);

    // ---- iterations 2..20: fused fast path ----
    for (int it = 0; it < 19; it++) {
        sink_fast<<<CH, blk>>>(out, r, c, p);
        comb_add<<<NT / 256, blk>>>(p, c);
    }

    final_exp_kernel<<<(unsigned)((size_t)NT * NT / 4 / 256), blk>>>(out, r, c);
}